// round 5
// baseline (speedup 1.0000x reference)
#include <cuda_runtime.h>
#include <cuda_bf16.h>

#define HID   2048
#define INTER 8192
#define NTOK  16384
#define NEXP  8

// Scratch (device globals: allocation-free per harness rules)
__device__ float         g_scale[NTOK];
__device__ __nv_bfloat16 g_h[(size_t)NTOK * INTER];

// ---------------------------------------------------------------------------
// Pass A: gate logits (fp32 exact) + scale = sum of top-2 logits per token
// one warp per token
// ---------------------------------------------------------------------------
__global__ __launch_bounds__(256) void gate_kernel(const float* __restrict__ X,
                                                   const float* __restrict__ GW) {
    int warp = blockIdx.x * 8 + (threadIdx.x >> 5);
    int lane = threadIdx.x & 31;
    if (warp >= NTOK) return;
    const float* xr = X + (size_t)warp * HID;
    float acc[NEXP];
#pragma unroll
    for (int e = 0; e < NEXP; e++) acc[e] = 0.f;
    for (int i = 0; i < HID / 32; i++) {
        int k = lane + 32 * i;
        float xv = xr[k];
        float4 g0 = *(const float4*)(GW + (size_t)k * NEXP);
        float4 g1 = *(const float4*)(GW + (size_t)k * NEXP + 4);
        acc[0] += xv * g0.x; acc[1] += xv * g0.y;
        acc[2] += xv * g0.z; acc[3] += xv * g0.w;
        acc[4] += xv * g1.x; acc[5] += xv * g1.y;
        acc[6] += xv * g1.z; acc[7] += xv * g1.w;
    }
#pragma unroll
    for (int e = 0; e < NEXP; e++) {
#pragma unroll
        for (int off = 16; off > 0; off >>= 1)
            acc[e] += __shfl_down_sync(0xffffffffu, acc[e], off);
    }
    if (lane == 0) {
        float m1 = -3.4e38f, m2 = -3.4e38f;
#pragma unroll
        for (int e = 0; e < NEXP; e++) {
            float v = acc[e];
            if (v > m1) { m2 = m1; m1 = v; }
            else if (v > m2) m2 = v;
        }
        g_scale[warp] = m1 + m2;
    }
}

// ---------------------------------------------------------------------------
// Pass B: h = relu(x @ up_w)^2  (bf16 mma.sync, fp32 accumulate, bf16 out)
// 128x128 block tile, 8 warps (2x4), warp tile 64x32, BK=32
// ---------------------------------------------------------------------------
__global__ __launch_bounds__(256) void up_kernel(const float* __restrict__ X,
                                                 const float* __restrict__ W) {
    __shared__ __nv_bfloat16 As[128][34];  // [m][k], padded
    __shared__ __nv_bfloat16 Bs[128][34];  // [n][k], padded (transposed tile)

    const int bm = blockIdx.y * 128, bn = blockIdx.x * 128;
    const int tid = threadIdx.x;
    const int wid = tid >> 5, lane = tid & 31;
    const int wm = (wid >> 2) * 64;  // warp m offset
    const int wn = (wid & 3) * 32;   // warp n offset
    const int g = lane >> 2, t = lane & 3;

    float c[4][4][4];
#pragma unroll
    for (int i = 0; i < 4; i++)
#pragma unroll
        for (int j = 0; j < 4; j++)
#pragma unroll
            for (int q = 0; q < 4; q++) c[i][j][q] = 0.f;

    for (int k0 = 0; k0 < HID; k0 += 32) {
        // A tile: X[bm:bm+128, k0:k0+32] fp32 -> bf16
#pragma unroll
        for (int it = 0; it < 4; it++) {
            int i = tid + it * 256;           // float4 id, 1024 total
            int row = i >> 3, c4 = (i & 7) << 2;
            float4 v = *(const float4*)(X + (size_t)(bm + row) * HID + k0 + c4);
            As[row][c4 + 0] = __float2bfloat16(v.x);
            As[row][c4 + 1] = __float2bfloat16(v.y);
            As[row][c4 + 2] = __float2bfloat16(v.z);
            As[row][c4 + 3] = __float2bfloat16(v.w);
        }
        // B tile: W[k0:k0+32, bn:bn+128] fp32 -> bf16, stored transposed [n][k]
#pragma unroll
        for (int it = 0; it < 4; it++) {
            int i = tid + it * 256;
            int kr = i >> 5, cn = (i & 31) << 2;
            float4 v = *(const float4*)(W + (size_t)(k0 + kr) * INTER + bn + cn);
            Bs[cn + 0][kr] = __float2bfloat16(v.x);
            Bs[cn + 1][kr] = __float2bfloat16(v.y);
            Bs[cn + 2][kr] = __float2bfloat16(v.z);
            Bs[cn + 3][kr] = __float2bfloat16(v.w);
        }
        __syncthreads();
#pragma unroll
        for (int ks = 0; ks < 32; ks += 16) {
            unsigned a[4][4], b[4][2];
#pragma unroll
            for (int mi = 0; mi < 4; mi++) {
                int r = wm + mi * 16;
                a[mi][0] = *(const unsigned*)&As[r + g][ks + t * 2];
                a[mi][1] = *(const unsigned*)&As[r + g + 8][ks + t * 2];
                a[mi][2] = *(const unsigned*)&As[r + g][ks + t * 2 + 8];
                a[mi][3] = *(const unsigned*)&As[r + g + 8][ks + t * 2 + 8];
            }
#pragma unroll
            for (int nj = 0; nj < 4; nj++) {
                int n = wn + nj * 8 + g;
                b[nj][0] = *(const unsigned*)&Bs[n][ks + t * 2];
                b[nj][1] = *(const unsigned*)&Bs[n][ks + t * 2 + 8];
            }
#pragma unroll
            for (int mi = 0; mi < 4; mi++)
#pragma unroll
                for (int nj = 0; nj < 4; nj++)
                    asm volatile(
                        "mma.sync.aligned.m16n8k16.row.col.f32.bf16.bf16.f32 "
                        "{%0,%1,%2,%3}, {%4,%5,%6,%7}, {%8,%9}, {%0,%1,%2,%3};"
                        : "+f"(c[mi][nj][0]), "+f"(c[mi][nj][1]),
                          "+f"(c[mi][nj][2]), "+f"(c[mi][nj][3])
                        : "r"(a[mi][0]), "r"(a[mi][1]), "r"(a[mi][2]), "r"(a[mi][3]),
                          "r"(b[nj][0]), "r"(b[nj][1]));
        }
        __syncthreads();
    }
    // epilogue: relu^2 -> bf16 -> g_h
#pragma unroll
    for (int mi = 0; mi < 4; mi++)
#pragma unroll
        for (int nj = 0; nj < 4; nj++) {
            int r0 = bm + wm + mi * 16 + g;
            int col = bn + wn + nj * 8 + t * 2;
            float v0 = c[mi][nj][0]; v0 = v0 > 0.f ? v0 * v0 : 0.f;
            float v1 = c[mi][nj][1]; v1 = v1 > 0.f ? v1 * v1 : 0.f;
            float v2 = c[mi][nj][2]; v2 = v2 > 0.f ? v2 * v2 : 0.f;
            float v3 = c[mi][nj][3]; v3 = v3 > 0.f ? v3 * v3 : 0.f;
            __nv_bfloat162 p01 = __floats2bfloat162_rn(v0, v1);
            __nv_bfloat162 p23 = __floats2bfloat162_rn(v2, v3);
            *(__nv_bfloat162*)(g_h + (size_t)r0 * INTER + col) = p01;
            *(__nv_bfloat162*)(g_h + (size_t)(r0 + 8) * INTER + col) = p23;
        }
}

__device__ __forceinline__ unsigned f2tf32(float f) {
    unsigned r;
    asm("cvt.rna.tf32.f32 %0, %1;" : "=r"(r) : "f"(f));
    return r;
}

// ---------------------------------------------------------------------------
// Pass C: y = h @ down_w  +  (scale[m] * x) @ expert_w
// loop1: bf16 mma K=8192 ; loop2: tf32 mma K=2048 ; same fp32 accumulators
// ---------------------------------------------------------------------------
__global__ __launch_bounds__(256) void down_expert_kernel(
    const float* __restrict__ X, const float* __restrict__ DW,
    const float* __restrict__ EW, float* __restrict__ Y) {
    __shared__ __nv_bfloat16 As[128][34];
    __shared__ __nv_bfloat16 Bs[128][34];
    __shared__ unsigned Af[128][17];   // tf32 bits, BK2=16
    __shared__ unsigned Bf[128][17];
    __shared__ float s_scale[128];

    const int bm = blockIdx.y * 128, bn = blockIdx.x * 128;
    const int tid = threadIdx.x;
    const int wid = tid >> 5, lane = tid & 31;
    const int wm = (wid >> 2) * 64;
    const int wn = (wid & 3) * 32;
    const int g = lane >> 2, t = lane & 3;

    if (tid < 128) s_scale[tid] = g_scale[bm + tid];

    float c[4][4][4];
#pragma unroll
    for (int i = 0; i < 4; i++)
#pragma unroll
        for (int j = 0; j < 4; j++)
#pragma unroll
            for (int q = 0; q < 4; q++) c[i][j][q] = 0.f;

    // ---- loop 1: h (bf16) @ down_w, K = INTER ----
    for (int k0 = 0; k0 < INTER; k0 += 32) {
#pragma unroll
        for (int it = 0; it < 2; it++) {
            int i = tid + it * 256;            // 8-elem chunk id, 512 total
            int row = i >> 2, c8 = (i & 3) << 3;
            uint4 u = *(const uint4*)(g_h + (size_t)(bm + row) * INTER + k0 + c8);
            unsigned* d = (unsigned*)&As[row][c8];
            const unsigned* s = (const unsigned*)&u;
            d[0] = s[0]; d[1] = s[1]; d[2] = s[2]; d[3] = s[3];
        }
#pragma unroll
        for (int it = 0; it < 4; it++) {
            int i = tid + it * 256;
            int kr = i >> 5, cn = (i & 31) << 2;
            float4 v = *(const float4*)(DW + (size_t)(k0 + kr) * HID + bn + cn);
            Bs[cn + 0][kr] = __float2bfloat16(v.x);
            Bs[cn + 1][kr] = __float2bfloat16(v.y);
            Bs[cn + 2][kr] = __float2bfloat16(v.z);
            Bs[cn + 3][kr] = __float2bfloat16(v.w);
        }
        __syncthreads();
#pragma unroll
        for (int ks = 0; ks < 32; ks += 16) {
            unsigned a[4][4], b[4][2];
#pragma unroll
            for (int mi = 0; mi < 4; mi++) {
                int r = wm + mi * 16;
                a[mi][0] = *(const unsigned*)&As[r + g][ks + t * 2];
                a[mi][1] = *(const unsigned*)&As[r + g + 8][ks + t * 2];
                a[mi][2] = *(const unsigned*)&As[r + g][ks + t * 2 + 8];
                a[mi][3] = *(const unsigned*)&As[r + g + 8][ks + t * 2 + 8];
            }
#pragma unroll
            for (int nj = 0; nj < 4; nj++) {
                int n = wn + nj * 8 + g;
                b[nj][0] = *(const unsigned*)&Bs[n][ks + t * 2];
                b[nj][1] = *(const unsigned*)&Bs[n][ks + t * 2 + 8];
            }
#pragma unroll
            for (int mi = 0; mi < 4; mi++)
#pragma unroll
                for (int nj = 0; nj < 4; nj++)
                    asm volatile(
                        "mma.sync.aligned.m16n8k16.row.col.f32.bf16.bf16.f32 "
                        "{%0,%1,%2,%3}, {%4,%5,%6,%7}, {%8,%9}, {%0,%1,%2,%3};"
                        : "+f"(c[mi][nj][0]), "+f"(c[mi][nj][1]),
                          "+f"(c[mi][nj][2]), "+f"(c[mi][nj][3])
                        : "r"(a[mi][0]), "r"(a[mi][1]), "r"(a[mi][2]), "r"(a[mi][3]),
                          "r"(b[nj][0]), "r"(b[nj][1]));
        }
        __syncthreads();
    }

    // ---- loop 2: (scale*x) @ expert_w, tf32, K = HID, BK2 = 16 ----
    for (int k0 = 0; k0 < HID; k0 += 16) {
#pragma unroll
        for (int it = 0; it < 2; it++) {
            int i = tid + it * 256;            // float4 id, 512 total
            int row = i >> 2, c4 = (i & 3) << 2;
            float4 v = *(const float4*)(X + (size_t)(bm + row) * HID + k0 + c4);
            float s = s_scale[row];
            Af[row][c4 + 0] = f2tf32(v.x * s);
            Af[row][c4 + 1] = f2tf32(v.y * s);
            Af[row][c4 + 2] = f2tf32(v.z * s);
            Af[row][c4 + 3] = f2tf32(v.w * s);
        }
#pragma unroll
        for (int it = 0; it < 2; it++) {
            int i = tid + it * 256;
            int kr = i >> 5, cn = (i & 31) << 2;
            float4 v = *(const float4*)(EW + (size_t)(k0 + kr) * HID + bn + cn);
            Bf[cn + 0][kr] = f2tf32(v.x);
            Bf[cn + 1][kr] = f2tf32(v.y);
            Bf[cn + 2][kr] = f2tf32(v.z);
            Bf[cn + 3][kr] = f2tf32(v.w);
        }
        __syncthreads();
#pragma unroll
        for (int ks = 0; ks < 16; ks += 8) {
            unsigned a[4][4], b[4][2];
#pragma unroll
            for (int mi = 0; mi < 4; mi++) {
                int r = wm + mi * 16;
                a[mi][0] = Af[r + g][ks + t];
                a[mi][1] = Af[r + g + 8][ks + t];
                a[mi][2] = Af[r + g][ks + t + 4];
                a[mi][3] = Af[r + g + 8][ks + t + 4];
            }
#pragma unroll
            for (int nj = 0; nj < 4; nj++) {
                int n = wn + nj * 8 + g;
                b[nj][0] = Bf[n][ks + t];
                b[nj][1] = Bf[n][ks + t + 4];
            }
#pragma unroll
            for (int mi = 0; mi < 4; mi++)
#pragma unroll
                for (int nj = 0; nj < 4; nj++)
                    asm volatile(
                        "mma.sync.aligned.m16n8k8.row.col.f32.tf32.tf32.f32 "
                        "{%0,%1,%2,%3}, {%4,%5,%6,%7}, {%8,%9}, {%0,%1,%2,%3};"
                        : "+f"(c[mi][nj][0]), "+f"(c[mi][nj][1]),
                          "+f"(c[mi][nj][2]), "+f"(c[mi][nj][3])
                        : "r"(a[mi][0]), "r"(a[mi][1]), "r"(a[mi][2]), "r"(a[mi][3]),
                          "r"(b[nj][0]), "r"(b[nj][1]));
        }
        __syncthreads();
    }

    // epilogue: write y (pre-layernorm) to d_out
#pragma unroll
    for (int mi = 0; mi < 4; mi++)
#pragma unroll
        for (int nj = 0; nj < 4; nj++) {
            int r0 = bm + wm + mi * 16 + g;
            int col = bn + wn + nj * 8 + t * 2;
            float2 p01 = make_float2(c[mi][nj][0], c[mi][nj][1]);
            float2 p23 = make_float2(c[mi][nj][2], c[mi][nj][3]);
            *(float2*)(Y + (size_t)r0 * HID + col) = p01;
            *(float2*)(Y + (size_t)(r0 + 8) * HID + col) = p23;
        }
}

// ---------------------------------------------------------------------------
// Pass D: in-place layernorm over d_out rows
// ---------------------------------------------------------------------------
__global__ __launch_bounds__(256) void ln_kernel(float* __restrict__ Y,
                                                 const float* __restrict__ gamma,
                                                 const float* __restrict__ beta) {
    int t = blockIdx.x;
    int tid = threadIdx.x;
    float* row = Y + (size_t)t * HID;
    float v[8];
    *(float4*)&v[0] = *(const float4*)(row + tid * 8);
    *(float4*)&v[4] = *(const float4*)(row + tid * 8 + 4);
    float s = 0.f, q = 0.f;
#pragma unroll
    for (int j = 0; j < 8; j++) { s += v[j]; q += v[j] * v[j]; }
#pragma unroll
    for (int off = 16; off > 0; off >>= 1) {
        s += __shfl_xor_sync(0xffffffffu, s, off);
        q += __shfl_xor_sync(0xffffffffu, q, off);
    }
    __shared__ float ss[8], sq[8];
    __shared__ float s_mu, s_rstd;
    int w = tid >> 5, lane = tid & 31;
    if (lane == 0) { ss[w] = s; sq[w] = q; }
    __syncthreads();
    if (tid == 0) {
        float S = 0.f, Q = 0.f;
#pragma unroll
        for (int i = 0; i < 8; i++) { S += ss[i]; Q += sq[i]; }
        float mu = S / (float)HID;
        float var = Q / (float)HID - mu * mu;
        s_mu = mu;
        s_rstd = rsqrtf(var + 1e-5f);
    }
    __syncthreads();
    float mu = s_mu, r = s_rstd;
    float o[8];
#pragma unroll
    for (int j = 0; j < 8; j++) {
        int cidx = tid * 8 + j;
        o[j] = (v[j] - mu) * r * gamma[cidx] + beta[cidx];
    }
    *(float4*)(row + tid * 8) = *(float4*)&o[0];
    *(float4*)(row + tid * 8 + 4) = *(float4*)&o[4];
}

// ---------------------------------------------------------------------------
extern "C" void kernel_launch(void* const* d_in, const int* in_sizes, int n_in,
                              void* d_out, int out_size) {
    const float* X     = (const float*)d_in[0];
    const float* GW    = (const float*)d_in[1];
    const float* UW    = (const float*)d_in[2];
    const float* DW    = (const float*)d_in[3];
    const float* EW    = (const float*)d_in[4];
    const float* GAMMA = (const float*)d_in[5];
    const float* BETA  = (const float*)d_in[6];
    float* Y = (float*)d_out;

    gate_kernel<<<NTOK / 8, 256>>>(X, GW);
    up_kernel<<<dim3(INTER / 128, NTOK / 128), 256>>>(X, UW);
    down_expert_kernel<<<dim3(HID / 128, NTOK / 128), 256>>>(X, DW, EW, Y);
    ln_kernel<<<NTOK, 256>>>(Y, GAMMA, BETA);
}

// round 8
// speedup vs baseline: 2.0329x; 2.0329x over previous
#include <cuda_runtime.h>
#include <cuda_bf16.h>
#include <cstdint>

#define HID   2048
#define INTER 8192
#define NTOK  16384
#define NEXP  8

// ---------------------------------------------------------------------------
// Device-global scratch (allocation-free per harness rules)
// ---------------------------------------------------------------------------
__device__ float         g_scale[NTOK];
__device__ __nv_bfloat16 g_h  [(size_t)NTOK * INTER];   // 256 MB
__device__ __nv_bfloat16 g_Xb [(size_t)NTOK * HID];     //  64 MB bf16(X)
__device__ float         g_Xs [(size_t)NTOK * HID];     // 128 MB tf32rna(scale*X)
__device__ __nv_bfloat16 g_UWt[(size_t)INTER * HID];    //  32 MB [n][k] bf16
__device__ __nv_bfloat16 g_DWt[(size_t)HID * INTER];    //  32 MB [n][k] bf16
__device__ float         g_EWt[(size_t)HID * HID];      //  16 MB [n][k] tf32rna

__device__ __forceinline__ unsigned f2tf32(float f) {
    unsigned r;
    asm("cvt.rna.tf32.f32 %0, %1;" : "=r"(r) : "f"(f));
    return r;
}
__device__ __forceinline__ void cp16(void* dst, const void* src) {
    unsigned d = (unsigned)__cvta_generic_to_shared(dst);
    asm volatile("cp.async.cg.shared.global [%0], [%1], 16;" :: "r"(d), "l"(src));
}

// ---------------------------------------------------------------------------
// GEMM geometry: block tile 128x128, 256 threads (8 warps 2x4, warp 64x32)
// K-stage = 128 bytes per row (64 bf16 or 32 tf32). SMEM row stride 144B
// (conflict-free: bank = (36*g + t) mod 32 covers all 32 banks).
// ---------------------------------------------------------------------------
#define ROWB   144
#define TILE_B (128 * ROWB)          // 18432 B (one operand tile)
#define STG_B  (2 * TILE_B)          // 36864 B (A+B, one stage)
#define GSMEM  (2 * STG_B)           // 73728 B (two stages)

// fill one stage: A tile (128 rows x 128B) + B tile (128 rows x 128B)
__device__ __forceinline__ void copy_stage(char* st, const char* pa, size_t lda,
                                           const char* pb, size_t ldb) {
    const int tid = threadIdx.x;
#pragma unroll
    for (int it = 0; it < 4; it++) {
        int c = tid + it * 256;                 // 1024 chunks of 16B
        int r = c >> 3, q = (c & 7) * 16;
        cp16(st + r * ROWB + q, pa + (size_t)r * lda + q);
    }
#pragma unroll
    for (int it = 0; it < 4; it++) {
        int c = tid + it * 256;
        int r = c >> 3, q = (c & 7) * 16;
        cp16(st + TILE_B + r * ROWB + q, pb + (size_t)r * ldb + q);
    }
    asm volatile("cp.async.commit_group;" ::: "memory");
}

// one 128B K-stage of MMAs.  Fragment byte offsets are identical for bf16
// (m16n8k16, 16 elems = 32B per step) and tf32 (m16n8k8, 8 elems = 32B).
template <bool TF32>
__device__ __forceinline__ void compute_stage(const char* Ab, const char* Bb,
                                              int wm, int wn, int g, int t,
                                              float (*c)[4][4]) {
#pragma unroll
    for (int ksi = 0; ksi < 4; ksi++) {
        const int ko = ksi * 32 + t * 4;
        unsigned a[4][4], b[4][2];
#pragma unroll
        for (int mi = 0; mi < 4; mi++) {
            const char* p0 = Ab + (size_t)(wm + mi * 16 + g) * ROWB + ko;
            const char* p1 = p0 + 8 * ROWB;
            a[mi][0] = *(const unsigned*)p0;
            a[mi][1] = *(const unsigned*)p1;
            a[mi][2] = *(const unsigned*)(p0 + 16);
            a[mi][3] = *(const unsigned*)(p1 + 16);
        }
#pragma unroll
        for (int nj = 0; nj < 4; nj++) {
            const char* p = Bb + (size_t)(wn + nj * 8 + g) * ROWB + ko;
            b[nj][0] = *(const unsigned*)p;
            b[nj][1] = *(const unsigned*)(p + 16);
        }
#pragma unroll
        for (int mi = 0; mi < 4; mi++)
#pragma unroll
            for (int nj = 0; nj < 4; nj++) {
                if (TF32)
                    asm volatile(
                        "mma.sync.aligned.m16n8k8.row.col.f32.tf32.tf32.f32 "
                        "{%0,%1,%2,%3}, {%4,%5,%6,%7}, {%8,%9}, {%0,%1,%2,%3};"
                        : "+f"(c[mi][nj][0]), "+f"(c[mi][nj][1]),
                          "+f"(c[mi][nj][2]), "+f"(c[mi][nj][3])
                        : "r"(a[mi][0]), "r"(a[mi][1]), "r"(a[mi][2]), "r"(a[mi][3]),
                          "r"(b[nj][0]), "r"(b[nj][1]));
                else
                    asm volatile(
                        "mma.sync.aligned.m16n8k16.row.col.f32.bf16.bf16.f32 "
                        "{%0,%1,%2,%3}, {%4,%5,%6,%7}, {%8,%9}, {%0,%1,%2,%3};"
                        : "+f"(c[mi][nj][0]), "+f"(c[mi][nj][1]),
                          "+f"(c[mi][nj][2]), "+f"(c[mi][nj][3])
                        : "r"(a[mi][0]), "r"(a[mi][1]), "r"(a[mi][2]), "r"(a[mi][3]),
                          "r"(b[nj][0]), "r"(b[nj][1]));
            }
    }
}

// full K loop over one operand pair; K advances 128 bytes per stage.
template <bool TF32>
__device__ __forceinline__ void run_phase(char* sm, const char* A, size_t lda,
                                          const char* B, size_t ldb, int ns,
                                          int wm, int wn, int g, int t,
                                          float (*c)[4][4]) {
    copy_stage(sm, A, lda, B, ldb);
    for (int s = 0; s < ns; s++) {
        int b = s & 1;
        if (s + 1 < ns) {
            copy_stage(sm + (b ^ 1) * STG_B,
                       A + (size_t)(s + 1) * 128, lda,
                       B + (size_t)(s + 1) * 128, ldb);
            asm volatile("cp.async.wait_group 1;" ::: "memory");
        } else {
            asm volatile("cp.async.wait_group 0;" ::: "memory");
        }
        __syncthreads();
        compute_stage<TF32>(sm + b * STG_B, sm + b * STG_B + TILE_B, wm, wn, g, t, c);
        __syncthreads();
    }
}

// ---------------------------------------------------------------------------
// up:  h = relu(Xb @ UWt^T)^2   (bf16, epilogue -> g_h bf16)
// ---------------------------------------------------------------------------
__global__ __launch_bounds__(256, 2)
void up_mma(const __nv_bfloat16* __restrict__ Xb, const __nv_bfloat16* __restrict__ Wt) {
    extern __shared__ char sm[];
    const int tid = threadIdx.x, wid = tid >> 5, lane = tid & 31;
    const int wm = (wid >> 2) * 64, wn = (wid & 3) * 32;
    const int g = lane >> 2, t = lane & 3;
    const size_t bm = (size_t)blockIdx.y * 128, bn = (size_t)blockIdx.x * 128;

    float c[4][4][4];
#pragma unroll
    for (int i = 0; i < 4; i++)
#pragma unroll
        for (int j = 0; j < 4; j++)
#pragma unroll
            for (int q = 0; q < 4; q++) c[i][j][q] = 0.f;

    run_phase<false>(sm, (const char*)(Xb + bm * HID), (size_t)HID * 2,
                     (const char*)(Wt + bn * HID), (size_t)HID * 2,
                     HID * 2 / 128, wm, wn, g, t, c);

#pragma unroll
    for (int mi = 0; mi < 4; mi++)
#pragma unroll
        for (int nj = 0; nj < 4; nj++) {
            size_t r0 = bm + wm + mi * 16 + g;
            size_t col = bn + wn + nj * 8 + t * 2;
            float v0 = c[mi][nj][0]; v0 = v0 > 0.f ? v0 * v0 : 0.f;
            float v1 = c[mi][nj][1]; v1 = v1 > 0.f ? v1 * v1 : 0.f;
            float v2 = c[mi][nj][2]; v2 = v2 > 0.f ? v2 * v2 : 0.f;
            float v3 = c[mi][nj][3]; v3 = v3 > 0.f ? v3 * v3 : 0.f;
            __nv_bfloat162 p01 = __floats2bfloat162_rn(v0, v1);
            __nv_bfloat162 p23 = __floats2bfloat162_rn(v2, v3);
            *(__nv_bfloat162*)(g_h + r0 * INTER + col) = p01;
            *(__nv_bfloat162*)(g_h + (r0 + 8) * INTER + col) = p23;
        }
}

// ---------------------------------------------------------------------------
// down+expert: Y = h @ DWt^T (bf16) + Xs @ EWt^T (tf32), shared accumulators
// ---------------------------------------------------------------------------
__global__ __launch_bounds__(256, 2)
void down_mma(float* __restrict__ Y) {
    extern __shared__ char sm[];
    const int tid = threadIdx.x, wid = tid >> 5, lane = tid & 31;
    const int wm = (wid >> 2) * 64, wn = (wid & 3) * 32;
    const int g = lane >> 2, t = lane & 3;
    const size_t bm = (size_t)blockIdx.y * 128, bn = (size_t)blockIdx.x * 128;

    float c[4][4][4];
#pragma unroll
    for (int i = 0; i < 4; i++)
#pragma unroll
        for (int j = 0; j < 4; j++)
#pragma unroll
            for (int q = 0; q < 4; q++) c[i][j][q] = 0.f;

    // phase 1: bf16  h[m][k] x DWt[n][k], K = INTER
    run_phase<false>(sm, (const char*)(g_h + bm * INTER), (size_t)INTER * 2,
                     (const char*)(g_DWt + bn * INTER), (size_t)INTER * 2,
                     INTER * 2 / 128, wm, wn, g, t, c);
    // phase 2: tf32  Xs[m][k] x EWt[n][k], K = HID, same accumulators
    run_phase<true>(sm, (const char*)(g_Xs + bm * HID), (size_t)HID * 4,
                    (const char*)(g_EWt + bn * HID), (size_t)HID * 4,
                    HID * 4 / 128, wm, wn, g, t, c);

#pragma unroll
    for (int mi = 0; mi < 4; mi++)
#pragma unroll
        for (int nj = 0; nj < 4; nj++) {
            size_t r0 = bm + wm + mi * 16 + g;
            size_t col = bn + wn + nj * 8 + t * 2;
            *(float2*)(Y + r0 * HID + col) = make_float2(c[mi][nj][0], c[mi][nj][1]);
            *(float2*)(Y + (r0 + 8) * HID + col) = make_float2(c[mi][nj][2], c[mi][nj][3]);
        }
}

// ---------------------------------------------------------------------------
// gate: fp32-exact logits, scale = sum of top-2 per token (one warp/token)
// ---------------------------------------------------------------------------
__global__ __launch_bounds__(256) void gate_kernel(const float* __restrict__ X,
                                                   const float* __restrict__ GW) {
    int warp = blockIdx.x * 8 + (threadIdx.x >> 5);
    int lane = threadIdx.x & 31;
    if (warp >= NTOK) return;
    const float* xr = X + (size_t)warp * HID;
    float acc[NEXP];
#pragma unroll
    for (int e = 0; e < NEXP; e++) acc[e] = 0.f;
    for (int i = 0; i < HID / 32; i++) {
        int k = lane + 32 * i;
        float xv = xr[k];
        float4 g0 = *(const float4*)(GW + (size_t)k * NEXP);
        float4 g1 = *(const float4*)(GW + (size_t)k * NEXP + 4);
        acc[0] += xv * g0.x; acc[1] += xv * g0.y;
        acc[2] += xv * g0.z; acc[3] += xv * g0.w;
        acc[4] += xv * g1.x; acc[5] += xv * g1.y;
        acc[6] += xv * g1.z; acc[7] += xv * g1.w;
    }
#pragma unroll
    for (int e = 0; e < NEXP; e++) {
#pragma unroll
        for (int off = 16; off > 0; off >>= 1)
            acc[e] += __shfl_down_sync(0xffffffffu, acc[e], off);
    }
    if (lane == 0) {
        float m1 = -3.4e38f, m2 = -3.4e38f;
#pragma unroll
        for (int e = 0; e < NEXP; e++) {
            float v = acc[e];
            if (v > m1) { m2 = m1; m1 = v; }
            else if (v > m2) m2 = v;
        }
        g_scale[warp] = m1 + m2;
    }
}

// ---------------------------------------------------------------------------
// prep: Xb = bf16(X);  Xs = tf32rna(scale[row] * X)
// ---------------------------------------------------------------------------
__global__ __launch_bounds__(256) void prep_x(const float* __restrict__ X) {
    size_t i = ((size_t)blockIdx.x * 256 + threadIdx.x) * 4;
    int row = (int)(i >> 11);
    float4 v = *(const float4*)(X + i);
    float s = g_scale[row];
    __nv_bfloat162 a = __floats2bfloat162_rn(v.x, v.y);
    __nv_bfloat162 b = __floats2bfloat162_rn(v.z, v.w);
    *(uint32_t*)(g_Xb + i)     = *(uint32_t*)&a;
    *(uint32_t*)(g_Xb + i + 2) = *(uint32_t*)&b;
    float4 w = make_float4(__uint_as_float(f2tf32(v.x * s)),
                           __uint_as_float(f2tf32(v.y * s)),
                           __uint_as_float(f2tf32(v.z * s)),
                           __uint_as_float(f2tf32(v.w * s)));
    *(float4*)(g_Xs + i) = w;
}

// ---------------------------------------------------------------------------
// transpose + convert: src fp32 [R][C] -> dst [C][R]
// ---------------------------------------------------------------------------
__global__ void tr_to_bf16(const float* __restrict__ S, __nv_bfloat16* __restrict__ D,
                           int R, int C) {
    __shared__ float t[32][33];
    int c0 = blockIdx.x * 32, r0 = blockIdx.y * 32;
    int tx = threadIdx.x, ty = threadIdx.y;
#pragma unroll
    for (int i = 0; i < 32; i += 8)
        t[ty + i][tx] = S[(size_t)(r0 + ty + i) * C + c0 + tx];
    __syncthreads();
#pragma unroll
    for (int i = 0; i < 32; i += 8)
        D[(size_t)(c0 + ty + i) * R + r0 + tx] = __float2bfloat16(t[tx][ty + i]);
}

__global__ void tr_to_tf32(const float* __restrict__ S, float* __restrict__ D,
                           int R, int C) {
    __shared__ float t[32][33];
    int c0 = blockIdx.x * 32, r0 = blockIdx.y * 32;
    int tx = threadIdx.x, ty = threadIdx.y;
#pragma unroll
    for (int i = 0; i < 32; i += 8)
        t[ty + i][tx] = S[(size_t)(r0 + ty + i) * C + c0 + tx];
    __syncthreads();
#pragma unroll
    for (int i = 0; i < 32; i += 8)
        D[(size_t)(c0 + ty + i) * R + r0 + tx] = __uint_as_float(f2tf32(t[tx][ty + i]));
}

// ---------------------------------------------------------------------------
// layernorm (in place)
// ---------------------------------------------------------------------------
__global__ __launch_bounds__(256) void ln_kernel(float* __restrict__ Y,
                                                 const float* __restrict__ gamma,
                                                 const float* __restrict__ beta) {
    int tok = blockIdx.x;
    int tid = threadIdx.x;
    float* row = Y + (size_t)tok * HID;
    float v[8];
    *(float4*)&v[0] = *(const float4*)(row + tid * 8);
    *(float4*)&v[4] = *(const float4*)(row + tid * 8 + 4);
    float s = 0.f, q = 0.f;
#pragma unroll
    for (int j = 0; j < 8; j++) { s += v[j]; q += v[j] * v[j]; }
#pragma unroll
    for (int off = 16; off > 0; off >>= 1) {
        s += __shfl_xor_sync(0xffffffffu, s, off);
        q += __shfl_xor_sync(0xffffffffu, q, off);
    }
    __shared__ float ss[8], sq[8];
    __shared__ float s_mu, s_rstd;
    int w = tid >> 5, lane = tid & 31;
    if (lane == 0) { ss[w] = s; sq[w] = q; }
    __syncthreads();
    if (tid == 0) {
        float S = 0.f, Q = 0.f;
#pragma unroll
        for (int i = 0; i < 8; i++) { S += ss[i]; Q += sq[i]; }
        float mu = S / (float)HID;
        float var = Q / (float)HID - mu * mu;
        s_mu = mu;
        s_rstd = rsqrtf(var + 1e-5f);
    }
    __syncthreads();
    float mu = s_mu, r = s_rstd;
    float o[8];
#pragma unroll
    for (int j = 0; j < 8; j++) {
        int cidx = tid * 8 + j;
        o[j] = (v[j] - mu) * r * gamma[cidx] + beta[cidx];
    }
    *(float4*)(row + tid * 8) = *(float4*)&o[0];
    *(float4*)(row + tid * 8 + 4) = *(float4*)&o[4];
}

// ---------------------------------------------------------------------------
extern "C" void kernel_launch(void* const* d_in, const int* in_sizes, int n_in,
                              void* d_out, int out_size) {
    const float* X     = (const float*)d_in[0];
    const float* GW    = (const float*)d_in[1];
    const float* UW    = (const float*)d_in[2];
    const float* DW    = (const float*)d_in[3];
    const float* EW    = (const float*)d_in[4];
    const float* GAMMA = (const float*)d_in[5];
    const float* BETA  = (const float*)d_in[6];
    float* Y = (float*)d_out;

    static int attr_done = 0;
    if (!attr_done) {
        cudaFuncSetAttribute(up_mma,   cudaFuncAttributeMaxDynamicSharedMemorySize, GSMEM);
        cudaFuncSetAttribute(down_mma, cudaFuncAttributeMaxDynamicSharedMemorySize, GSMEM);
        attr_done = 1;
    }

    __nv_bfloat16* uwt; cudaGetSymbolAddress((void**)&uwt, g_UWt);
    __nv_bfloat16* dwt; cudaGetSymbolAddress((void**)&dwt, g_DWt);
    float*         ewt; cudaGetSymbolAddress((void**)&ewt, g_EWt);
    __nv_bfloat16* xb;  cudaGetSymbolAddress((void**)&xb,  g_Xb);

    gate_kernel<<<NTOK / 8, 256>>>(X, GW);
    prep_x<<<(NTOK * HID / 4) / 256, 256>>>(X);
    tr_to_bf16<<<dim3(INTER / 32, HID / 32),   dim3(32, 8)>>>(UW, uwt, HID, INTER);
    tr_to_bf16<<<dim3(HID / 32,   INTER / 32), dim3(32, 8)>>>(DW, dwt, INTER, HID);
    tr_to_tf32<<<dim3(HID / 32,   HID / 32),   dim3(32, 8)>>>(EW, ewt, HID, HID);

    up_mma  <<<dim3(INTER / 128, NTOK / 128), 256, GSMEM>>>(xb, uwt);
    down_mma<<<dim3(HID / 128,   NTOK / 128), 256, GSMEM>>>(Y);
    ln_kernel<<<NTOK, 256>>>(Y, GAMMA, BETA);
}